// round 13
// baseline (speedup 1.0000x reference)
#include <cuda_runtime.h>
#include <math.h>

#define M_ANCH   589824
#define NCLS     80
#define K_TOP    1000
#define CAND_CAP 8192
#define HSHIFT   18                     /* 14-bit logit histogram */
#define NHBINS   16384
#define GRID_P1  576
#define GRID_R   148
#define NTHR     256
#define NWARPS   (GRID_R * (NTHR / 32)) /* 1184 */
#define NKEY4    (M_ANCH / 4)           /* 147456 */
#define RSTRIDE  (GRID_R * NTHR)        /* 37888 */
#define CAPC     256                    /* staged NMS columns */
#define IMG_INV  (1.0f/2048.0f)
#define SCALE_CLAMP 4.1351665567423560f /* log(1000/16) */

// ---------------- scratch (device globals; no allocations allowed) ----------
__device__ unsigned            g_key[M_ANCH];       // logit-ordered bits
__device__ unsigned            g_hist[NHBINS];      // starts 0; re-zeroed in K3
__device__ unsigned            g_candCount;
__device__ unsigned long long  g_cand[CAND_CAP];    // (sigmoid-key<<32)|~idx
__device__ float4              g_boxes[K_TOP];
__device__ int                 g_labels[K_TOP];
__device__ unsigned            g_validw[32];
__device__ unsigned            g_colnz[32];
__device__ unsigned            g_mask[K_TOP * 32];

// ---------------- helpers ---------------------------------------------------
__device__ __forceinline__ unsigned f2ord(float f) {
    unsigned u = __float_as_uint(f);
    return (u & 0x80000000u) ? ~u : (u | 0x80000000u);
}
__device__ __forceinline__ float ord2f(unsigned o) {
    return (o & 0x80000000u) ? __uint_as_float(o & 0x7FFFFFFFu)
                             : __uint_as_float(~o);
}
// Sigmoid matching XLA lowering of lax.logistic on GPU (bit-stable vs ref).
__device__ __forceinline__ float ref_sigmoid(float x) {
    float e = expf(-x);
    return __fdiv_rn(1.0f, __fadd_rn(1.0f, e));
}

// ---------------- K1: rowmax (pipelined) + logit key + 14-bit hist ----------
__global__ void __launch_bounds__(NTHR, 4)
k_p1(const float* __restrict__ cls) {
    __shared__ unsigned shp[NHBINS / 2];     // packed u16 pair counters, 32KB
    const int t = threadIdx.x;
    const int b = blockIdx.x;
    const int warpId = t >> 5;
    const int lane = t & 31;
    const int g = lane >> 2;
    const int gl = lane & 3;

    for (int e = t; e < NHBINS / 2; e += NTHR) shp[e] = 0u;
    __syncthreads();

    const int rowBase = b * 1024 + warpId * 128 + g;
    const float* basep = cls + (size_t)rowBase * NCLS + gl * 4;

    float4 A0, A1, A2, A3, A4;
    {
        const float* rp = basep;
        A0 = *(const float4*)(rp);
        A1 = *(const float4*)(rp + 16);
        A2 = *(const float4*)(rp + 32);
        A3 = *(const float4*)(rp + 48);
        A4 = *(const float4*)(rp + 64);
    }
#pragma unroll 2
    for (int p = 0; p < 16; p++) {
        int pn = (p < 15) ? p + 1 : 15;
        const float* rp = basep + (size_t)pn * 8 * NCLS;
        float4 B0 = *(const float4*)(rp);
        float4 B1 = *(const float4*)(rp + 16);
        float4 B2 = *(const float4*)(rp + 32);
        float4 B3 = *(const float4*)(rp + 48);
        float4 B4 = *(const float4*)(rp + 64);

        float m = fmaxf(fmaxf(A0.x, A0.y), fmaxf(A0.z, A0.w));
        m = fmaxf(m, fmaxf(fmaxf(A1.x, A1.y), fmaxf(A1.z, A1.w)));
        m = fmaxf(m, fmaxf(fmaxf(A2.x, A2.y), fmaxf(A2.z, A2.w)));
        m = fmaxf(m, fmaxf(fmaxf(A3.x, A3.y), fmaxf(A3.z, A3.w)));
        m = fmaxf(m, fmaxf(fmaxf(A4.x, A4.y), fmaxf(A4.z, A4.w)));
        m = fmaxf(m, __shfl_xor_sync(0xffffffffu, m, 1));
        m = fmaxf(m, __shfl_xor_sync(0xffffffffu, m, 2));
        if (gl == 0) {
            unsigned key = f2ord(m);
            g_key[rowBase + p * 8] = key;
            unsigned bin = key >> HSHIFT;
            atomicAdd(&shp[bin >> 1], 1u << ((bin & 1u) << 4));
        }
        A0 = B0; A1 = B1; A2 = B2; A3 = B3; A4 = B4;
    }
    __syncthreads();
    for (int e = t; e < NHBINS / 2; e += NTHR) {
        unsigned v = shp[e];
        unsigned lo = v & 0xFFFFu, hi = v >> 16;
        if (lo) atomicAdd(&g_hist[2 * e], lo);
        if (hi) atomicAdd(&g_hist[2 * e + 1], hi);
    }
}

// ---------------- K2: find threshold (redundant per block) + compact --------
__global__ void __launch_bounds__(NTHR, 4)
k_sel() {
    __shared__ unsigned ssum[NTHR];
    __shared__ unsigned sbest;
    const int t = threadIdx.x;
    const int b = blockIdx.x;
    const int lane = t & 31;

    unsigned s = 0;
#pragma unroll 8
    for (int e = 0; e < 64; e++) s += g_hist[t * 64 + e];
    ssum[t] = s;
    if (t == 0) sbest = 0u;
    __syncthreads();
    for (int off = 1; off < NTHR; off <<= 1) {
        unsigned a = (t + off < NTHR) ? ssum[t + off] : 0u;
        __syncthreads();
        ssum[t] += a;
        __syncthreads();
    }
    unsigned run = ssum[t] - s;
    unsigned best = 0;
    for (int e = 63; e >= 0; e--) {
        run += g_hist[t * 64 + e];
        if (run >= K_TOP) { best = (unsigned)(t * 64 + e); break; }
    }
    if (best) atomicMax(&sbest, best);
    __syncthreads();
    unsigned B = sbest;
    unsigned thr = (B > 0 ? B - 1 : 0) << HSHIFT;   // one-bin tie margin

    const uint4* kp = (const uint4*)g_key;
#pragma unroll
    for (int it = 0; it < 4; it++) {
        int idx = b * NTHR + t + it * RSTRIDE;
        bool inb = idx < NKEY4;
        uint4 k4 = inb ? kp[idx] : make_uint4(0u, 0u, 0u, 0u);
        int i0 = idx * 4;
        unsigned keys[4] = { k4.x, k4.y, k4.z, k4.w };
#pragma unroll
        for (int c = 0; c < 4; c++) {
            bool f = inb && (keys[c] >= thr);
            unsigned bal = __ballot_sync(0xffffffffu, f);
            if (bal) {
                unsigned base;
                if (lane == 0)
                    base = atomicAdd(&g_candCount, (unsigned)__popc(bal));
                base = __shfl_sync(0xffffffffu, base, 0);
                if (f) {
                    unsigned pos = base + __popc(bal & ((1u << lane) - 1u));
                    if (pos < CAND_CAP) {
                        unsigned skey = f2ord(ref_sigmoid(ord2f(keys[c])));
                        g_cand[pos] = ((unsigned long long)skey << 32) |
                                      (unsigned)(~(i0 + c));
                    }
                }
            }
        }
    }
    if (b == 100 && t < 32) g_validw[t] = 0u;
}

// ---------------- K3: warp-per-candidate rank + cooperative decode ----------
__global__ void __launch_bounds__(NTHR, 2)
k_rank(const float* __restrict__ cls, const float* __restrict__ reg,
       const float* __restrict__ anc, float* __restrict__ out) {
    extern __shared__ unsigned long long sc[];
    const int t = threadIdx.x;
    const int b = blockIdx.x;
    const int warpId = t >> 5;
    const int lane = t & 31;
    unsigned cnt = min(g_candCount, (unsigned)CAND_CAP);

    for (unsigned j = t; j < cnt; j += NTHR) sc[j] = g_cand[j];
    __syncthreads();

    int gw = b * (NTHR / 32) + warpId;
    for (unsigned c = (unsigned)gw; c < cnt; c += NWARPS) {
        unsigned long long my = sc[c];
        unsigned r = 0;
        for (unsigned j = lane; j < cnt; j += 32) r += (sc[j] > my);
        r = __reduce_add_sync(0xffffffffu, r);
        if (r < K_TOP) {
            int i = (int)(~(unsigned)(my & 0xFFFFFFFFULL));
            int j = (int)r;
            const float4* row = (const float4*)(cls + (size_t)i * NCLS);
            unsigned long long bkey = 0ULL;
            if (lane < NCLS / 4) {
                float4 v = row[lane];
                float s0 = ref_sigmoid(v.x), s1 = ref_sigmoid(v.y);
                float s2 = ref_sigmoid(v.z), s3 = ref_sigmoid(v.w);
                unsigned long long k0 = ((unsigned long long)f2ord(s0) << 32) |
                                        (unsigned)(~(4 * lane + 0));
                unsigned long long k1 = ((unsigned long long)f2ord(s1) << 32) |
                                        (unsigned)(~(4 * lane + 1));
                unsigned long long k2 = ((unsigned long long)f2ord(s2) << 32) |
                                        (unsigned)(~(4 * lane + 2));
                unsigned long long k3 = ((unsigned long long)f2ord(s3) << 32) |
                                        (unsigned)(~(4 * lane + 3));
                bkey = max(max(k0, k1), max(k2, k3));
            }
#pragma unroll
            for (int off = 16; off >= 1; off >>= 1) {
                unsigned long long o = __shfl_xor_sync(0xffffffffu, bkey, off);
                if (o > bkey) bkey = o;
            }
            if (lane == 0) {
                float best = ord2f((unsigned)(bkey >> 32));
                int bl = (int)(~(unsigned)(bkey & 0xFFFFFFFFULL));
                float4 rg = ((const float4*)reg)[i];
                float4 an = ((const float4*)anc)[i];
                float ox = fminf(fmaxf(rg.x * an.z, -32.0f), 32.0f);
                float oy = fminf(fmaxf(rg.y * an.w, -32.0f), 32.0f);
                float cx = an.x + ox, cy = an.y + oy;
                float w = an.z * expf(fminf(rg.z, SCALE_CLAMP));
                float h = an.w * expf(fminf(rg.w, SCALE_CLAMP));
                float x1 = fminf(fmaxf((cx - 0.5f * w) * IMG_INV, 0.0f), 1.0f);
                float y1 = fminf(fmaxf((cy - 0.5f * h) * IMG_INV, 0.0f), 1.0f);
                float x2 = fminf(fmaxf((cx + 0.5f * w) * IMG_INV, 0.0f), 1.0f);
                float y2 = fminf(fmaxf((cy + 0.5f * h) * IMG_INV, 0.0f), 1.0f);
                out[4 * j + 0] = x1; out[4 * j + 1] = y1;
                out[4 * j + 2] = x2; out[4 * j + 3] = y2;
                out[4000 + j] = best;
                out[5000 + j] = (float)bl;
                g_boxes[j] = make_float4(x1, y1, x2, y2);
                g_labels[j] = bl;
                if (best >= 0.05f)
                    atomicOr(&g_validw[j >> 5], 1u << (j & 31));
            }
        }
    }
    // cleanup for next run: hist + colnz (colnz written later by k_mask)
    {
        int z = b * NTHR + t;
        if (z < NHBINS) g_hist[z] = 0u;
        if (b == 0 && t < 32) g_colnz[t] = 0u;
    }
}

// ---------------- K4: suppression mask (smem-staged boxes, no barrier) ------
__global__ void __launch_bounds__(NTHR, 1)
k_mask() {
    __shared__ float4 s_box[K_TOP];            // 16 KB
    __shared__ int    s_lab[K_TOP];            //  4 KB
    const int t = threadIdx.x;
    const int b = blockIdx.x;
    const int warpId = t >> 5;
    const int lane = t & 31;

    for (int idx = t; idx < K_TOP; idx += NTHR) {
        s_box[idx] = g_boxes[idx];
        s_lab[idx] = g_labels[idx];
    }
    __syncthreads();

    int gw = b * (NTHR / 32) + warpId;
    for (int task = gw; task < K_TOP * 32; task += GRID_R * (NTHR / 32)) {
        int i = task >> 5, W = task & 31;
        float4 bi = s_box[i];
        int li = s_lab[i];
        float ai = (bi.z - bi.x) * (bi.w - bi.y);
        int j = W * 32 + lane;
        bool sup = false;
        if (j < i && s_lab[j] == li) {
            float4 bj = s_box[j];
            float xx1 = fmaxf(bi.x, bj.x), yy1 = fmaxf(bi.y, bj.y);
            float xx2 = fminf(bi.z, bj.z), yy2 = fminf(bi.w, bj.w);
            float ww = fmaxf(1e-10f, xx2 - xx1);
            float hh = fmaxf(1e-10f, yy2 - yy1);
            float inter = ww * hh;
            float aj = (bj.z - bj.x) * (bj.w - bj.y);
            float iou = inter / (ai + aj - inter + 1e-10f);
            sup = iou > 0.6f;
        }
        unsigned bits = __ballot_sync(0xffffffffu, sup);
        if (lane == 0) {
            g_mask[task] = bits;
            if (bits) atomicOr(&g_colnz[i >> 5], 1u << (i & 31));
        }
    }
    if (b == 5 && t == 0) g_candCount = 0u;
}

// ---------------- K5: single-block sparse greedy NMS ------------------------
__global__ void __launch_bounds__(1024, 1)
k_nms(float* __restrict__ out) {
    __shared__ unsigned s_list[1024];
    __shared__ unsigned s_cols[CAPC * 32];     // 32 KB
    __shared__ unsigned s_C;
    const int t = threadIdx.x;
    const int lane = t & 31;

    // build ordered nonzero-column list (warp 0)
    if (t < 32) {
        unsigned cz = g_colnz[t];
        unsigned pc = __popc(cz);
        unsigned pre = pc;
#pragma unroll
        for (int off = 1; off < 32; off <<= 1) {
            unsigned v = __shfl_up_sync(0xffffffffu, pre, off);
            if (lane >= off) pre += v;
        }
        unsigned start = pre - pc;              // exclusive prefix
        unsigned word = cz, k = 0;
        while (word) {
            int bbit = __ffs(word) - 1;
            word &= word - 1u;
            s_list[start + k] = (unsigned)(t * 32 + bbit);
            k++;
        }
        if (t == 31) s_C = pre;
    }
    __syncthreads();
    unsigned C = s_C;

    // stage the first min(C, CAPC) suppression columns into smem (1024 thr)
    unsigned CS = min(C, (unsigned)CAPC);
    for (unsigned idx = t; idx < CS * 32; idx += 1024) {
        unsigned k = idx >> 5, l2 = idx & 31;
        s_cols[idx] = g_mask[s_list[k] * 32 + l2];
    }
    __syncthreads();

    // serial greedy over nonzero columns only (warp 0)
    if (t < 32) {
        unsigned vw = g_validw[t];
        unsigned cz = g_colnz[t];
        unsigned kw = vw & ~cz;                 // zero-column: keep = valid
        for (unsigned k = 0; k < C; k++) {
            unsigned i = s_list[k];
            unsigned colw = (k < CAPC) ? s_cols[k * 32 + t]
                                       : g_mask[i * 32 + t];
            bool ov = __any_sync(0xffffffffu, (colw & kw) != 0u);
            unsigned vb = (__shfl_sync(0xffffffffu, vw, i >> 5) >> (i & 31)) & 1u;
            bool kp = (vb != 0u) && !ov;
            if (kp && (unsigned)t == (i >> 5)) kw |= (1u << (i & 31));
        }
#pragma unroll
        for (int e = 0; e < 32; e++) {
            int i = t * 32 + e;
            if (i < K_TOP) out[6000 + i] = ((kw >> e) & 1u) ? 1.0f : 0.0f;
        }
    }
}

// ---------------- launcher ---------------------------------------------------
extern "C" void kernel_launch(void* const* d_in, const int* in_sizes, int n_in,
                              void* d_out, int out_size) {
    const float* cls = (const float*)d_in[0];
    const float* reg = (const float*)d_in[1];
    const float* anc = (const float*)d_in[2];
    float* out = (float*)d_out;
    (void)in_sizes; (void)n_in; (void)out_size;

    cudaFuncSetAttribute(k_rank, cudaFuncAttributeMaxDynamicSharedMemorySize,
                         CAND_CAP * (int)sizeof(unsigned long long));

    k_p1<<<GRID_P1, NTHR>>>(cls);
    k_sel<<<GRID_R, NTHR>>>();
    k_rank<<<GRID_R, NTHR, CAND_CAP * sizeof(unsigned long long)>>>(cls, reg, anc, out);
    k_mask<<<GRID_R, NTHR>>>();
    k_nms<<<1, 1024>>>(out);
}

// round 14
// speedup vs baseline: 1.0290x; 1.0290x over previous
#include <cuda_runtime.h>
#include <math.h>

#define M_ANCH   589824
#define NCLS     80
#define K_TOP    1000
#define CAND_CAP 8192
#define PAIR_CAP 4096
#define HSHIFT   18                     /* 14-bit logit histogram */
#define NHBINS   16384
#define GRID_P1  576
#define GRID_R   148
#define NTHR     256
#define NWARPS   (GRID_R * (NTHR / 32)) /* 1184 */
#define NKEY4    (M_ANCH / 4)           /* 147456 */
#define RSTRIDE  (GRID_R * NTHR)        /* 37888 */
#define IMG_INV  (1.0f/2048.0f)
#define SCALE_CLAMP 4.1351665567423560f /* log(1000/16) */

// ---------------- scratch (device globals; no allocations allowed) ----------
__device__ unsigned            g_key[M_ANCH];       // logit-ordered bits
__device__ unsigned            g_hist[NHBINS];      // starts 0; re-zeroed in K3
__device__ unsigned            g_candCount;
__device__ unsigned long long  g_cand[CAND_CAP];    // (sigmoid-key<<32)|~idx
__device__ float4              g_boxes[K_TOP];
__device__ int                 g_labels[K_TOP];
__device__ unsigned            g_validw[32];

// ---------------- helpers ---------------------------------------------------
__device__ __forceinline__ unsigned f2ord(float f) {
    unsigned u = __float_as_uint(f);
    return (u & 0x80000000u) ? ~u : (u | 0x80000000u);
}
__device__ __forceinline__ float ord2f(unsigned o) {
    return (o & 0x80000000u) ? __uint_as_float(o & 0x7FFFFFFFu)
                             : __uint_as_float(~o);
}
// Sigmoid matching XLA lowering of lax.logistic on GPU (bit-stable vs ref).
__device__ __forceinline__ float ref_sigmoid(float x) {
    float e = expf(-x);
    return __fdiv_rn(1.0f, __fadd_rn(1.0f, e));
}

// ---------------- K1: rowmax (pipelined) + logit key + 14-bit hist ----------
__global__ void __launch_bounds__(NTHR, 4)
k_p1(const float* __restrict__ cls) {
    __shared__ unsigned shp[NHBINS / 2];     // packed u16 pair counters, 32KB
    const int t = threadIdx.x;
    const int b = blockIdx.x;
    const int warpId = t >> 5;
    const int lane = t & 31;
    const int g = lane >> 2;
    const int gl = lane & 3;

    for (int e = t; e < NHBINS / 2; e += NTHR) shp[e] = 0u;
    __syncthreads();

    const int rowBase = b * 1024 + warpId * 128 + g;
    const float* basep = cls + (size_t)rowBase * NCLS + gl * 4;

    float4 A0, A1, A2, A3, A4;
    {
        const float* rp = basep;
        A0 = *(const float4*)(rp);
        A1 = *(const float4*)(rp + 16);
        A2 = *(const float4*)(rp + 32);
        A3 = *(const float4*)(rp + 48);
        A4 = *(const float4*)(rp + 64);
    }
#pragma unroll 2
    for (int p = 0; p < 16; p++) {
        int pn = (p < 15) ? p + 1 : 15;
        const float* rp = basep + (size_t)pn * 8 * NCLS;
        float4 B0 = *(const float4*)(rp);
        float4 B1 = *(const float4*)(rp + 16);
        float4 B2 = *(const float4*)(rp + 32);
        float4 B3 = *(const float4*)(rp + 48);
        float4 B4 = *(const float4*)(rp + 64);

        float m = fmaxf(fmaxf(A0.x, A0.y), fmaxf(A0.z, A0.w));
        m = fmaxf(m, fmaxf(fmaxf(A1.x, A1.y), fmaxf(A1.z, A1.w)));
        m = fmaxf(m, fmaxf(fmaxf(A2.x, A2.y), fmaxf(A2.z, A2.w)));
        m = fmaxf(m, fmaxf(fmaxf(A3.x, A3.y), fmaxf(A3.z, A3.w)));
        m = fmaxf(m, fmaxf(fmaxf(A4.x, A4.y), fmaxf(A4.z, A4.w)));
        m = fmaxf(m, __shfl_xor_sync(0xffffffffu, m, 1));
        m = fmaxf(m, __shfl_xor_sync(0xffffffffu, m, 2));
        if (gl == 0) {
            unsigned key = f2ord(m);
            g_key[rowBase + p * 8] = key;
            unsigned bin = key >> HSHIFT;
            atomicAdd(&shp[bin >> 1], 1u << ((bin & 1u) << 4));
        }
        A0 = B0; A1 = B1; A2 = B2; A3 = B3; A4 = B4;
    }
    __syncthreads();
    for (int e = t; e < NHBINS / 2; e += NTHR) {
        unsigned v = shp[e];
        unsigned lo = v & 0xFFFFu, hi = v >> 16;
        if (lo) atomicAdd(&g_hist[2 * e], lo);
        if (hi) atomicAdd(&g_hist[2 * e + 1], hi);
    }
}

// ---------------- K2: find threshold (redundant per block) + compact --------
__global__ void __launch_bounds__(NTHR, 4)
k_sel() {
    __shared__ unsigned ssum[NTHR];
    __shared__ unsigned sbest;
    const int t = threadIdx.x;
    const int b = blockIdx.x;
    const int lane = t & 31;

    unsigned s = 0;
#pragma unroll 8
    for (int e = 0; e < 64; e++) s += g_hist[t * 64 + e];
    ssum[t] = s;
    if (t == 0) sbest = 0u;
    __syncthreads();
    for (int off = 1; off < NTHR; off <<= 1) {
        unsigned a = (t + off < NTHR) ? ssum[t + off] : 0u;
        __syncthreads();
        ssum[t] += a;
        __syncthreads();
    }
    unsigned run = ssum[t] - s;
    unsigned best = 0;
    for (int e = 63; e >= 0; e--) {
        run += g_hist[t * 64 + e];
        if (run >= K_TOP) { best = (unsigned)(t * 64 + e); break; }
    }
    if (best) atomicMax(&sbest, best);
    __syncthreads();
    unsigned B = sbest;
    unsigned thr = (B > 0 ? B - 1 : 0) << HSHIFT;   // one-bin tie margin

    const uint4* kp = (const uint4*)g_key;
#pragma unroll
    for (int it = 0; it < 4; it++) {
        int idx = b * NTHR + t + it * RSTRIDE;
        bool inb = idx < NKEY4;
        uint4 k4 = inb ? kp[idx] : make_uint4(0u, 0u, 0u, 0u);
        int i0 = idx * 4;
        unsigned keys[4] = { k4.x, k4.y, k4.z, k4.w };
#pragma unroll
        for (int c = 0; c < 4; c++) {
            bool f = inb && (keys[c] >= thr);
            unsigned bal = __ballot_sync(0xffffffffu, f);
            if (bal) {
                unsigned base;
                if (lane == 0)
                    base = atomicAdd(&g_candCount, (unsigned)__popc(bal));
                base = __shfl_sync(0xffffffffu, base, 0);
                if (f) {
                    unsigned pos = base + __popc(bal & ((1u << lane) - 1u));
                    if (pos < CAND_CAP) {
                        unsigned skey = f2ord(ref_sigmoid(ord2f(keys[c])));
                        g_cand[pos] = ((unsigned long long)skey << 32) |
                                      (unsigned)(~(i0 + c));
                    }
                }
            }
        }
    }
    if (b == 100 && t < 32) g_validw[t] = 0u;
}

// ---------------- K3: warp-per-candidate rank + cooperative decode ----------
__global__ void __launch_bounds__(NTHR, 2)
k_rank(const float* __restrict__ cls, const float* __restrict__ reg,
       const float* __restrict__ anc, float* __restrict__ out) {
    extern __shared__ unsigned long long sc[];
    const int t = threadIdx.x;
    const int b = blockIdx.x;
    const int warpId = t >> 5;
    const int lane = t & 31;
    unsigned cnt = min(g_candCount, (unsigned)CAND_CAP);

    for (unsigned j = t; j < cnt; j += NTHR) sc[j] = g_cand[j];
    __syncthreads();

    int gw = b * (NTHR / 32) + warpId;
    for (unsigned c = (unsigned)gw; c < cnt; c += NWARPS) {
        unsigned long long my = sc[c];
        unsigned r = 0;
        for (unsigned j = lane; j < cnt; j += 32) r += (sc[j] > my);
        r = __reduce_add_sync(0xffffffffu, r);
        if (r < K_TOP) {
            int i = (int)(~(unsigned)(my & 0xFFFFFFFFULL));
            int j = (int)r;
            const float4* row = (const float4*)(cls + (size_t)i * NCLS);
            unsigned long long bkey = 0ULL;
            if (lane < NCLS / 4) {
                float4 v = row[lane];
                float s0 = ref_sigmoid(v.x), s1 = ref_sigmoid(v.y);
                float s2 = ref_sigmoid(v.z), s3 = ref_sigmoid(v.w);
                unsigned long long k0 = ((unsigned long long)f2ord(s0) << 32) |
                                        (unsigned)(~(4 * lane + 0));
                unsigned long long k1 = ((unsigned long long)f2ord(s1) << 32) |
                                        (unsigned)(~(4 * lane + 1));
                unsigned long long k2 = ((unsigned long long)f2ord(s2) << 32) |
                                        (unsigned)(~(4 * lane + 2));
                unsigned long long k3 = ((unsigned long long)f2ord(s3) << 32) |
                                        (unsigned)(~(4 * lane + 3));
                bkey = max(max(k0, k1), max(k2, k3));
            }
#pragma unroll
            for (int off = 16; off >= 1; off >>= 1) {
                unsigned long long o = __shfl_xor_sync(0xffffffffu, bkey, off);
                if (o > bkey) bkey = o;
            }
            if (lane == 0) {
                float best = ord2f((unsigned)(bkey >> 32));
                int bl = (int)(~(unsigned)(bkey & 0xFFFFFFFFULL));
                float4 rg = ((const float4*)reg)[i];
                float4 an = ((const float4*)anc)[i];
                float ox = fminf(fmaxf(rg.x * an.z, -32.0f), 32.0f);
                float oy = fminf(fmaxf(rg.y * an.w, -32.0f), 32.0f);
                float cx = an.x + ox, cy = an.y + oy;
                float w = an.z * expf(fminf(rg.z, SCALE_CLAMP));
                float h = an.w * expf(fminf(rg.w, SCALE_CLAMP));
                float x1 = fminf(fmaxf((cx - 0.5f * w) * IMG_INV, 0.0f), 1.0f);
                float y1 = fminf(fmaxf((cy - 0.5f * h) * IMG_INV, 0.0f), 1.0f);
                float x2 = fminf(fmaxf((cx + 0.5f * w) * IMG_INV, 0.0f), 1.0f);
                float y2 = fminf(fmaxf((cy + 0.5f * h) * IMG_INV, 0.0f), 1.0f);
                out[4 * j + 0] = x1; out[4 * j + 1] = y1;
                out[4 * j + 2] = x2; out[4 * j + 3] = y2;
                out[4000 + j] = best;
                out[5000 + j] = (float)bl;
                g_boxes[j] = make_float4(x1, y1, x2, y2);
                g_labels[j] = bl;
                if (best >= 0.05f)
                    atomicOr(&g_validw[j >> 5], 1u << (j & 31));
            }
        }
    }
    // cleanup for next run: hist
    {
        int z = b * NTHR + t;
        if (z < NHBINS) g_hist[z] = 0u;
    }
}

// ---------------- K4: class-bucketed pair NMS (one block) -------------------
__global__ void __launch_bounds__(1024, 1)
k_nms2(float* __restrict__ out) {
    __shared__ float4         s_box[K_TOP];      // 16 KB
    __shared__ int            s_lab[K_TOP];      //  4 KB
    __shared__ unsigned short s_ord[K_TOP];      //  2 KB class-sorted ids
    __shared__ int            s_slot[K_TOP];     //  4 KB within-class slot
    __shared__ int            s_cnt[NCLS];
    __shared__ int            s_off[NCLS + 1];
    __shared__ unsigned       s_pairs[PAIR_CAP]; // 16 KB  (i<<16)|j
    __shared__ unsigned       s_np;
    __shared__ unsigned       s_colnz[32];
    __shared__ unsigned       s_keepw[32];
    const int t = threadIdx.x;
    const int lane = t & 31;
    const int w = t >> 5;

    // load candidates; init counters
    if (t < K_TOP) { s_box[t] = g_boxes[t]; s_lab[t] = g_labels[t]; }
    if (t < NCLS) s_cnt[t] = 0;
    if (t < 32) s_colnz[t] = 0u;
    if (t == 0) { s_np = 0u; g_candCount = 0u; }   // reset for next run
    __syncthreads();

    // counting sort by class
    if (t < K_TOP) s_slot[t] = atomicAdd(&s_cnt[s_lab[t]], 1);
    __syncthreads();
    if (t == 0) {
        int acc = 0;
        for (int c = 0; c < NCLS; c++) { s_off[c] = acc; acc += s_cnt[c]; }
        s_off[NCLS] = acc;
    }
    __syncthreads();
    if (t < K_TOP) s_ord[s_off[s_lab[t]] + s_slot[t]] = (unsigned short)t;
    __syncthreads();

    // within-class pair tests: warp w handles classes w, w+32, w+64
    for (int c = w; c < NCLS; c += 32) {
        int base = s_off[c], n = s_cnt[c];
        int npair = n * (n - 1) / 2;
        for (int pidx = lane; pidx < npair; pidx += 32) {
            // triangular decode: a in [1,n), b in [0,a)
            int a = (int)((sqrtf(8.0f * (float)pidx + 1.0f) + 1.0f) * 0.5f);
            while (a * (a - 1) / 2 > pidx) a--;
            while ((a + 1) * a / 2 <= pidx) a++;
            int bq = pidx - a * (a - 1) / 2;
            int ia = (int)s_ord[base + a], jb = (int)s_ord[base + bq];
            int i = ia > jb ? ia : jb;
            int j = ia > jb ? jb : ia;
            float4 bi = s_box[i], bj = s_box[j];
            float xx1 = fmaxf(bi.x, bj.x), yy1 = fmaxf(bi.y, bj.y);
            float xx2 = fminf(bi.z, bj.z), yy2 = fminf(bi.w, bj.w);
            float ww = fmaxf(1e-10f, xx2 - xx1);
            float hh = fmaxf(1e-10f, yy2 - yy1);
            float inter = ww * hh;
            float ai = (bi.z - bi.x) * (bi.w - bi.y);
            float aj = (bj.z - bj.x) * (bj.w - bj.y);
            float iou = inter / (ai + aj - inter + 1e-10f);
            if (iou > 0.6f) {
                unsigned p = atomicAdd(&s_np, 1u);
                if (p < PAIR_CAP)
                    s_pairs[p] = ((unsigned)i << 16) | (unsigned)j;
                atomicOr(&s_colnz[i >> 5], 1u << (i & 31));
            }
        }
    }
    __syncthreads();

    // warp 0: sparse serial greedy over nonzero-column candidates
    if (t < 32) {
        unsigned vw = g_validw[lane];
        unsigned cz = s_colnz[lane];
        s_keepw[lane] = vw & ~cz;               // zero-column: keep = valid
        __syncwarp();
        unsigned np = min(s_np, (unsigned)PAIR_CAP);
        for (int w2 = 0; w2 < 32; w2++) {
            unsigned word = s_colnz[w2];
            while (word) {
                int bbit = __ffs(word) - 1;
                word &= word - 1u;
                unsigned i = (unsigned)(w2 * 32 + bbit);
                bool ov = false;
                for (unsigned p = lane; p < np; p += 32) {
                    unsigned pr = s_pairs[p];
                    if ((pr >> 16) == i) {
                        unsigned j = pr & 0xFFFFu;
                        if ((s_keepw[j >> 5] >> (j & 31u)) & 1u) ov = true;
                    }
                }
                ov = __any_sync(0xffffffffu, ov);
                unsigned vb = (__shfl_sync(0xffffffffu, vw, w2) >> bbit) & 1u;
                if (lane == 0 && vb && !ov) s_keepw[w2] |= (1u << bbit);
                __syncwarp();
            }
        }
        unsigned kwf = s_keepw[lane];
#pragma unroll
        for (int e = 0; e < 32; e++) {
            int i = lane * 32 + e;
            if (i < K_TOP) out[6000 + i] = ((kwf >> e) & 1u) ? 1.0f : 0.0f;
        }
    }
}

// ---------------- launcher ---------------------------------------------------
extern "C" void kernel_launch(void* const* d_in, const int* in_sizes, int n_in,
                              void* d_out, int out_size) {
    const float* cls = (const float*)d_in[0];
    const float* reg = (const float*)d_in[1];
    const float* anc = (const float*)d_in[2];
    float* out = (float*)d_out;
    (void)in_sizes; (void)n_in; (void)out_size;

    cudaFuncSetAttribute(k_rank, cudaFuncAttributeMaxDynamicSharedMemorySize,
                         CAND_CAP * (int)sizeof(unsigned long long));

    k_p1<<<GRID_P1, NTHR>>>(cls);
    k_sel<<<GRID_R, NTHR>>>();
    k_rank<<<GRID_R, NTHR, CAND_CAP * sizeof(unsigned long long)>>>(cls, reg, anc, out);
    k_nms2<<<1, 1024>>>(out);
}

// round 15
// speedup vs baseline: 1.0918x; 1.0611x over previous
#include <cuda_runtime.h>
#include <math.h>

#define M_ANCH   589824
#define NCLS     80
#define K_TOP    1000
#define CAND_CAP 8192
#define PAIR_CAP 4096
#define CAPC     512                    /* column-bitmask capacity */
#define HSHIFT   18                     /* 14-bit logit histogram */
#define NHBINS   16384
#define GRID_P1  576
#define GRID_R   148
#define NTHR     256
#define NWARPS   (GRID_R * (NTHR / 32)) /* 1184 */
#define NKEY4    (M_ANCH / 4)           /* 147456 */
#define RSTRIDE  (GRID_R * NTHR)        /* 37888 */
#define IMG_INV  (1.0f/2048.0f)
#define SCALE_CLAMP 4.1351665567423560f /* log(1000/16) */

// ---------------- scratch (device globals; no allocations allowed) ----------
__device__ unsigned            g_key[M_ANCH];       // logit-ordered bits
__device__ unsigned            g_hist[NHBINS];      // starts 0; re-zeroed in K3
__device__ unsigned            g_candCount;
__device__ unsigned long long  g_cand[CAND_CAP];    // (sigmoid-key<<32)|~idx
__device__ float4              g_boxes[K_TOP];
__device__ int                 g_labels[K_TOP];
__device__ unsigned            g_validw[32];

// ---------------- helpers ---------------------------------------------------
__device__ __forceinline__ unsigned f2ord(float f) {
    unsigned u = __float_as_uint(f);
    return (u & 0x80000000u) ? ~u : (u | 0x80000000u);
}
__device__ __forceinline__ float ord2f(unsigned o) {
    return (o & 0x80000000u) ? __uint_as_float(o & 0x7FFFFFFFu)
                             : __uint_as_float(~o);
}
// Sigmoid matching XLA lowering of lax.logistic on GPU (bit-stable vs ref).
__device__ __forceinline__ float ref_sigmoid(float x) {
    float e = expf(-x);
    return __fdiv_rn(1.0f, __fadd_rn(1.0f, e));
}

// ---------------- K1: rowmax (pipelined) + logit key + 14-bit hist ----------
__global__ void __launch_bounds__(NTHR, 4)
k_p1(const float* __restrict__ cls) {
    __shared__ unsigned shp[NHBINS / 2];     // packed u16 pair counters, 32KB
    const int t = threadIdx.x;
    const int b = blockIdx.x;
    const int warpId = t >> 5;
    const int lane = t & 31;
    const int g = lane >> 2;
    const int gl = lane & 3;

    for (int e = t; e < NHBINS / 2; e += NTHR) shp[e] = 0u;
    __syncthreads();

    const int rowBase = b * 1024 + warpId * 128 + g;
    const float* basep = cls + (size_t)rowBase * NCLS + gl * 4;

    float4 A0, A1, A2, A3, A4;
    {
        const float* rp = basep;
        A0 = *(const float4*)(rp);
        A1 = *(const float4*)(rp + 16);
        A2 = *(const float4*)(rp + 32);
        A3 = *(const float4*)(rp + 48);
        A4 = *(const float4*)(rp + 64);
    }
#pragma unroll 2
    for (int p = 0; p < 16; p++) {
        int pn = (p < 15) ? p + 1 : 15;
        const float* rp = basep + (size_t)pn * 8 * NCLS;
        float4 B0 = *(const float4*)(rp);
        float4 B1 = *(const float4*)(rp + 16);
        float4 B2 = *(const float4*)(rp + 32);
        float4 B3 = *(const float4*)(rp + 48);
        float4 B4 = *(const float4*)(rp + 64);

        float m = fmaxf(fmaxf(A0.x, A0.y), fmaxf(A0.z, A0.w));
        m = fmaxf(m, fmaxf(fmaxf(A1.x, A1.y), fmaxf(A1.z, A1.w)));
        m = fmaxf(m, fmaxf(fmaxf(A2.x, A2.y), fmaxf(A2.z, A2.w)));
        m = fmaxf(m, fmaxf(fmaxf(A3.x, A3.y), fmaxf(A3.z, A3.w)));
        m = fmaxf(m, fmaxf(fmaxf(A4.x, A4.y), fmaxf(A4.z, A4.w)));
        m = fmaxf(m, __shfl_xor_sync(0xffffffffu, m, 1));
        m = fmaxf(m, __shfl_xor_sync(0xffffffffu, m, 2));
        if (gl == 0) {
            unsigned key = f2ord(m);
            g_key[rowBase + p * 8] = key;
            unsigned bin = key >> HSHIFT;
            atomicAdd(&shp[bin >> 1], 1u << ((bin & 1u) << 4));
        }
        A0 = B0; A1 = B1; A2 = B2; A3 = B3; A4 = B4;
    }
    __syncthreads();
    for (int e = t; e < NHBINS / 2; e += NTHR) {
        unsigned v = shp[e];
        unsigned lo = v & 0xFFFFu, hi = v >> 16;
        if (lo) atomicAdd(&g_hist[2 * e], lo);
        if (hi) atomicAdd(&g_hist[2 * e + 1], hi);
    }
}

// ---------------- K2: find threshold (register-resident) + compact ----------
__global__ void __launch_bounds__(NTHR)
k_sel() {
    __shared__ unsigned ssum[NTHR];
    __shared__ unsigned sbest;
    const int t = threadIdx.x;
    const int b = blockIdx.x;
    const int lane = t & 31;

    // load this thread's 64 bins as independent LDGs, keep in registers
    unsigned h[64];
#pragma unroll
    for (int e = 0; e < 64; e++) h[e] = g_hist[t * 64 + e];
    unsigned s = 0;
#pragma unroll
    for (int e = 0; e < 64; e++) s += h[e];
    ssum[t] = s;
    if (t == 0) sbest = 0u;
    __syncthreads();
    for (int off = 1; off < NTHR; off <<= 1) {
        unsigned a = (t + off < NTHR) ? ssum[t + off] : 0u;
        __syncthreads();
        ssum[t] += a;
        __syncthreads();
    }
    unsigned run = ssum[t] - s;          // strictly-higher threads' total
    unsigned best = 0;
#pragma unroll
    for (int e = 63; e >= 0; e--) {      // branch-free reverse scan in regs
        run += h[e];
        if (run >= K_TOP && best == 0u) best = (unsigned)(t * 64 + e);
    }
    if (best) atomicMax(&sbest, best);
    __syncthreads();
    unsigned B = sbest;
    unsigned thr = (B > 0 ? B - 1 : 0) << HSHIFT;   // one-bin tie margin

    const uint4* kp = (const uint4*)g_key;
#pragma unroll
    for (int it = 0; it < 4; it++) {
        int idx = b * NTHR + t + it * RSTRIDE;
        bool inb = idx < NKEY4;
        uint4 k4 = inb ? kp[idx] : make_uint4(0u, 0u, 0u, 0u);
        int i0 = idx * 4;
        unsigned keys[4] = { k4.x, k4.y, k4.z, k4.w };
#pragma unroll
        for (int c = 0; c < 4; c++) {
            bool f = inb && (keys[c] >= thr);
            unsigned bal = __ballot_sync(0xffffffffu, f);
            if (bal) {
                unsigned base;
                if (lane == 0)
                    base = atomicAdd(&g_candCount, (unsigned)__popc(bal));
                base = __shfl_sync(0xffffffffu, base, 0);
                if (f) {
                    unsigned pos = base + __popc(bal & ((1u << lane) - 1u));
                    if (pos < CAND_CAP) {
                        unsigned skey = f2ord(ref_sigmoid(ord2f(keys[c])));
                        g_cand[pos] = ((unsigned long long)skey << 32) |
                                      (unsigned)(~(i0 + c));
                    }
                }
            }
        }
    }
    if (b == 100 && t < 32) g_validw[t] = 0u;
}

// ---------------- K3: warp-per-candidate rank + cooperative decode ----------
__global__ void __launch_bounds__(NTHR, 2)
k_rank(const float* __restrict__ cls, const float* __restrict__ reg,
       const float* __restrict__ anc, float* __restrict__ out) {
    extern __shared__ unsigned long long sc[];
    const int t = threadIdx.x;
    const int b = blockIdx.x;
    const int warpId = t >> 5;
    const int lane = t & 31;
    unsigned cnt = min(g_candCount, (unsigned)CAND_CAP);

    for (unsigned j = t; j < cnt; j += NTHR) sc[j] = g_cand[j];
    __syncthreads();

    int gw = b * (NTHR / 32) + warpId;
    for (unsigned c = (unsigned)gw; c < cnt; c += NWARPS) {
        unsigned long long my = sc[c];
        unsigned r = 0;
        for (unsigned j = lane; j < cnt; j += 32) r += (sc[j] > my);
        r = __reduce_add_sync(0xffffffffu, r);
        if (r < K_TOP) {
            int i = (int)(~(unsigned)(my & 0xFFFFFFFFULL));
            int j = (int)r;
            const float4* row = (const float4*)(cls + (size_t)i * NCLS);
            unsigned long long bkey = 0ULL;
            if (lane < NCLS / 4) {
                float4 v = row[lane];
                float s0 = ref_sigmoid(v.x), s1 = ref_sigmoid(v.y);
                float s2 = ref_sigmoid(v.z), s3 = ref_sigmoid(v.w);
                unsigned long long k0 = ((unsigned long long)f2ord(s0) << 32) |
                                        (unsigned)(~(4 * lane + 0));
                unsigned long long k1 = ((unsigned long long)f2ord(s1) << 32) |
                                        (unsigned)(~(4 * lane + 1));
                unsigned long long k2 = ((unsigned long long)f2ord(s2) << 32) |
                                        (unsigned)(~(4 * lane + 2));
                unsigned long long k3 = ((unsigned long long)f2ord(s3) << 32) |
                                        (unsigned)(~(4 * lane + 3));
                bkey = max(max(k0, k1), max(k2, k3));
            }
#pragma unroll
            for (int off = 16; off >= 1; off >>= 1) {
                unsigned long long o = __shfl_xor_sync(0xffffffffu, bkey, off);
                if (o > bkey) bkey = o;
            }
            if (lane == 0) {
                float best = ord2f((unsigned)(bkey >> 32));
                int bl = (int)(~(unsigned)(bkey & 0xFFFFFFFFULL));
                float4 rg = ((const float4*)reg)[i];
                float4 an = ((const float4*)anc)[i];
                float ox = fminf(fmaxf(rg.x * an.z, -32.0f), 32.0f);
                float oy = fminf(fmaxf(rg.y * an.w, -32.0f), 32.0f);
                float cx = an.x + ox, cy = an.y + oy;
                float w = an.z * expf(fminf(rg.z, SCALE_CLAMP));
                float h = an.w * expf(fminf(rg.w, SCALE_CLAMP));
                float x1 = fminf(fmaxf((cx - 0.5f * w) * IMG_INV, 0.0f), 1.0f);
                float y1 = fminf(fmaxf((cy - 0.5f * h) * IMG_INV, 0.0f), 1.0f);
                float x2 = fminf(fmaxf((cx + 0.5f * w) * IMG_INV, 0.0f), 1.0f);
                float y2 = fminf(fmaxf((cy + 0.5f * h) * IMG_INV, 0.0f), 1.0f);
                out[4 * j + 0] = x1; out[4 * j + 1] = y1;
                out[4 * j + 2] = x2; out[4 * j + 3] = y2;
                out[4000 + j] = best;
                out[5000 + j] = (float)bl;
                g_boxes[j] = make_float4(x1, y1, x2, y2);
                g_labels[j] = bl;
                if (best >= 0.05f)
                    atomicOr(&g_validw[j >> 5], 1u << (j & 31));
            }
        }
    }
    // cleanup for next run: hist
    {
        int z = b * NTHR + t;
        if (z < NHBINS) g_hist[z] = 0u;
    }
}

// ---------------- K4: class-bucketed pair NMS with column bitmasks ----------
struct NmsShm {
    float4         box[K_TOP];
    int            lab[K_TOP];
    unsigned short ord[K_TOP];
    unsigned short slot[K_TOP];
    unsigned short map[K_TOP];
    unsigned short list[1024];
    int            cnt[NCLS];
    int            off[NCLS + 1];
    unsigned       pairs[PAIR_CAP];
    unsigned       cols[CAPC * 32];
    unsigned       np, C, colnz[32], keepw[32];
};

__global__ void __launch_bounds__(1024, 1)
k_nms2(float* __restrict__ out) {
    extern __shared__ char dyn[];
    NmsShm* sh = (NmsShm*)dyn;
    const int t = threadIdx.x;
    const int lane = t & 31;
    const int w = t >> 5;

    if (t < K_TOP) { sh->box[t] = g_boxes[t]; sh->lab[t] = g_labels[t]; }
    if (t < NCLS) sh->cnt[t] = 0;
    if (t < 32) sh->colnz[t] = 0u;
    if (t == 0) { sh->np = 0u; g_candCount = 0u; }   // reset for next run
    __syncthreads();

    // counting sort by class
    if (t < K_TOP) sh->slot[t] = (unsigned short)atomicAdd(&sh->cnt[sh->lab[t]], 1);
    __syncthreads();
    if (t == 0) {
        int acc = 0;
        for (int c = 0; c < NCLS; c++) { sh->off[c] = acc; acc += sh->cnt[c]; }
        sh->off[NCLS] = acc;
    }
    __syncthreads();
    if (t < K_TOP) sh->ord[sh->off[sh->lab[t]] + sh->slot[t]] = (unsigned short)t;
    __syncthreads();

    // within-class pair tests: warp w handles classes w, w+32, w+64
    for (int c = w; c < NCLS; c += 32) {
        int base = sh->off[c], n = sh->cnt[c];
        int npair = n * (n - 1) / 2;
        for (int pidx = lane; pidx < npair; pidx += 32) {
            int a = (int)((sqrtf(8.0f * (float)pidx + 1.0f) + 1.0f) * 0.5f);
            while (a * (a - 1) / 2 > pidx) a--;
            while ((a + 1) * a / 2 <= pidx) a++;
            int bq = pidx - a * (a - 1) / 2;
            int ia = (int)sh->ord[base + a], jb = (int)sh->ord[base + bq];
            int i = ia > jb ? ia : jb;
            int j = ia > jb ? jb : ia;
            float4 bi = sh->box[i], bj = sh->box[j];
            float xx1 = fmaxf(bi.x, bj.x), yy1 = fmaxf(bi.y, bj.y);
            float xx2 = fminf(bi.z, bj.z), yy2 = fminf(bi.w, bj.w);
            float ww = fmaxf(1e-10f, xx2 - xx1);
            float hh = fmaxf(1e-10f, yy2 - yy1);
            float inter = ww * hh;
            float ai = (bi.z - bi.x) * (bi.w - bi.y);
            float aj = (bj.z - bj.x) * (bj.w - bj.y);
            float iou = inter / (ai + aj - inter + 1e-10f);
            if (iou > 0.6f) {
                unsigned p = atomicAdd(&sh->np, 1u);
                if (p < PAIR_CAP)
                    sh->pairs[p] = ((unsigned)i << 16) | (unsigned)j;
                atomicOr(&sh->colnz[i >> 5], 1u << (i & 31));
            }
        }
    }
    __syncthreads();

    // build ordered nonzero-column list (warp 0)
    if (t < 32) {
        unsigned cz = sh->colnz[lane];
        unsigned pc = __popc(cz);
        unsigned pre = pc;
#pragma unroll
        for (int off = 1; off < 32; off <<= 1) {
            unsigned v = __shfl_up_sync(0xffffffffu, pre, off);
            if (lane >= off) pre += v;
        }
        unsigned start = pre - pc;
        unsigned word = cz, k = 0;
        while (word) {
            int bbit = __ffs(word) - 1;
            word &= word - 1u;
            sh->list[start + k] = (unsigned short)(lane * 32 + bbit);
            k++;
        }
        if (lane == 31) sh->C = pre;
    }
    __syncthreads();
    unsigned C = sh->C;
    unsigned CS = min(C, (unsigned)CAPC);
    unsigned np = min(sh->np, (unsigned)PAIR_CAP);

    // candidate -> list-slot map; zero the used column bitmasks
    for (unsigned k = t; k < C; k += 1024) sh->map[sh->list[k]] = (unsigned short)k;
    for (unsigned idx = t; idx < CS * 32; idx += 1024) sh->cols[idx] = 0u;
    __syncthreads();

    // scatter pairs into column bitmasks (all threads)
    for (unsigned p = t; p < np; p += 1024) {
        unsigned pr = sh->pairs[p];
        unsigned i = pr >> 16, j = pr & 0xFFFFu;
        unsigned k = sh->map[i];
        if (k < CAPC)
            atomicOr(&sh->cols[k * 32 + (j >> 5)], 1u << (j & 31));
    }
    __syncthreads();

    // warp 0: serial greedy, one LDS + one vote per nonzero-column candidate
    if (t < 32) {
        unsigned vw = g_validw[lane];
        unsigned kw = vw & ~sh->colnz[lane];    // zero-column: keep = valid
        bool fb_init = false;
        for (unsigned k = 0; k < C; k++) {
            unsigned i = (unsigned)sh->list[k];
            bool ov;
            if (k < CAPC) {
                unsigned colw = sh->cols[k * 32 + lane];
                ov = __any_sync(0xffffffffu, (colw & kw) != 0u);
            } else {
                if (!fb_init) { sh->keepw[lane] = kw; __syncwarp(); fb_init = true; }
                bool myov = false;
                for (unsigned p = lane; p < np; p += 32) {
                    unsigned pr = sh->pairs[p];
                    if ((pr >> 16) == i) {
                        unsigned j = pr & 0xFFFFu;
                        if ((sh->keepw[j >> 5] >> (j & 31u)) & 1u) myov = true;
                    }
                }
                ov = __any_sync(0xffffffffu, myov);
            }
            unsigned vb = (__shfl_sync(0xffffffffu, vw, i >> 5) >> (i & 31u)) & 1u;
            bool kp = (vb != 0u) && !ov;
            if (kp && (unsigned)lane == (i >> 5)) {
                kw |= (1u << (i & 31u));
                if (fb_init) sh->keepw[lane] = kw;
            }
            if (fb_init) __syncwarp();
        }
#pragma unroll
        for (int e = 0; e < 32; e++) {
            int i = lane * 32 + e;
            if (i < K_TOP) out[6000 + i] = ((kw >> e) & 1u) ? 1.0f : 0.0f;
        }
    }
}

// ---------------- launcher ---------------------------------------------------
extern "C" void kernel_launch(void* const* d_in, const int* in_sizes, int n_in,
                              void* d_out, int out_size) {
    const float* cls = (const float*)d_in[0];
    const float* reg = (const float*)d_in[1];
    const float* anc = (const float*)d_in[2];
    float* out = (float*)d_out;
    (void)in_sizes; (void)n_in; (void)out_size;

    cudaFuncSetAttribute(k_rank, cudaFuncAttributeMaxDynamicSharedMemorySize,
                         CAND_CAP * (int)sizeof(unsigned long long));
    cudaFuncSetAttribute(k_nms2, cudaFuncAttributeMaxDynamicSharedMemorySize,
                         (int)sizeof(NmsShm));

    k_p1<<<GRID_P1, NTHR>>>(cls);
    k_sel<<<GRID_R, NTHR>>>();
    k_rank<<<GRID_R, NTHR, CAND_CAP * sizeof(unsigned long long)>>>(cls, reg, anc, out);
    k_nms2<<<1, 1024, sizeof(NmsShm)>>>(out);
}